// round 14
// baseline (speedup 1.0000x reference)
#include <cuda_runtime.h>
#include <cuda_bf16.h>

#define N_TOT 65536
#define VBS 128
#define NCHUNK 512
#define EPS_F 1e-5f
#define GAMMA_F 1.5f
#define S05C 0.70710678118654752440f

typedef unsigned int u32;

// smem layout (bytes)
#define OFF_A    0        // A hi: 4 x 16KB (128B-row swizzled) ; lo at +65536
#define OFF_ALO  65536
#define OFF_W    131072   // W ring: 3 x 32KB (16KB hi + 16KB lo, 64B-row SW64)
// stats alias ring slot 2 (dead during epilogues; epi_gbn top-sync guards it)
#define OFF_PS   196608   // 4 x 256 fp32
#define OFF_PQ   200704
#define OFF_CA   204800
#define OFF_CB   205824
#define OFF_REX  206848   // 4 x 3 x 128 fp32
#define OFF_TAU  212992
#define SMEM_TOTAL 229376

// weights: 22 files (11 chunks x 2 k-halves) x 32KB (16KB hi + 16KB lo)
__device__ __align__(16) unsigned char g_wp[22*32768];

__device__ __forceinline__ u32 smem_u32(const void* p){
  u32 a; asm("{ .reg .u64 t; cvta.to.shared.u64 t, %1; cvt.u32.u64 %0, t; }"
             : "=r"(a) : "l"(p)); return a;
}
__device__ __forceinline__ float sigf(float x){
  return __fdividef(1.0f, 1.0f + __expf(-x));
}
__device__ __forceinline__ void split2(float a, float b, u32& hp, u32& lp){
  __nv_bfloat16 ha=__float2bfloat16(a), hb=__float2bfloat16(b);
  __nv_bfloat16 la=__float2bfloat16(a-__bfloat162float(ha));
  __nv_bfloat16 lb=__float2bfloat16(b-__bfloat162float(hb));
  hp = ((u32)__bfloat16_as_ushort(hb)<<16) | __bfloat16_as_ushort(ha);
  lp = ((u32)__bfloat16_as_ushort(lb)<<16) | __bfloat16_as_ushort(la);
}
__device__ __forceinline__ float bflo(u32 v){
  return __bfloat162float(__ushort_as_bfloat16((unsigned short)(v&0xffffu)));
}
__device__ __forceinline__ float bfhi(u32 v){
  return __bfloat162float(__ushort_as_bfloat16((unsigned short)(v>>16)));
}

#define LDSM4(r, a) \
  asm volatile("ldmatrix.sync.aligned.m8n8.x4.shared.b16 {%0,%1,%2,%3}, [%4];" \
    : "=r"((r)[0]),"=r"((r)[1]),"=r"((r)[2]),"=r"((r)[3]) : "r"(a))
#define MMA(d, a, b0, b1) \
  asm volatile("mma.sync.aligned.m16n8k16.row.col.f32.bf16.bf16.f32 " \
    "{%0,%1,%2,%3},{%4,%5,%6,%7},{%8,%9},{%0,%1,%2,%3};" \
    : "+f"((d)[0]),"+f"((d)[1]),"+f"((d)[2]),"+f"((d)[3]) \
    : "r"((a)[0]),"r"((a)[1]),"r"((a)[2]),"r"((a)[3]),"r"(b0),"r"(b1))
#define CPA(dst, src) \
  asm volatile("cp.async.cg.shared.global [%0], [%1], 16;" :: "r"(dst), "l"(src))
#define CPA4(dst, src) do{ CPA((dst),(src)); CPA((dst)+16,(src)+16); \
  CPA((dst)+32,(src)+32); CPA((dst)+48,(src)+48);}while(0)
#define CP_COMMIT() asm volatile("cp.async.commit_group;" ::: "memory")
#define CP_WAIT1()  asm volatile("cp.async.wait_group 1;" ::: "memory")

// column permutation: quarter q owns u-cols d=q*32..+31 (n'=q*64+pos) and
// g-cols d=128+q*32..+31 (n'=q*64+32+pos)
__device__ __forceinline__ int permn(int n){
  return (n < 128) ? ((n>>5)*64 + (n&31))
                   : (((n-128)>>5)*64 + 32 + ((n-128)&31));
}

// prep: fp32 W -> bf16 hi/lo, permuted cols, SW64 64B-row k32 half-chunk files
__global__ void prep_weights(const float* __restrict__ w_att,
                             const float* __restrict__ w_s1,
                             const float* __restrict__ w_s2,
                             const float* __restrict__ w_d1,
                             const float* __restrict__ w_d2){
  int t = blockIdx.x; const float* W; int K, kc;
  if (t == 0)     { W = w_att; K = 64;  kc = 0;   }
  else if (t < 5) { W = w_s1;  K = 256; kc = t-1; }
  else if (t < 7) { W = w_s2;  K = 128; kc = t-5; }
  else if (t < 9) { W = w_d1;  K = 128; kc = t-7; }
  else            { W = w_d2;  K = 128; kc = t-9; }
  for (int idx = threadIdx.x; idx < 16384; idx += 256){
    int n = idx >> 6, k = idx & 63;
    float w = W[n*K + kc*64 + k];
    __nv_bfloat16 hi = __float2bfloat16(w);
    __nv_bfloat16 lo = __float2bfloat16(w - __bfloat162float(hi));
    int np = permn(n);
    int file = t*2 + (k>>5);
    int cb = (k&31)*2;
    int off = np*64 + (cb ^ ((np&6)<<3));   // SW64 swizzle on 64B rows
    *(__nv_bfloat16*)(g_wp + (size_t)file*32768 + off)         = hi;
    *(__nv_bfloat16*)(g_wp + (size_t)file*32768 + 16384 + off) = lo;
  }
}

// C[128 x 256(n')] = A[128 x KH*32] * W^T, 3-term bf16 split.
// Ring-3 cp.async pipeline. MMA terms grouped across independent acc tiles
// (breaks acc RAW chains); B fragments register-double-buffered (breaks the
// LDS-burst / MMA-burst convoy).
template<int KH>
__device__ __forceinline__ void run_gemm(u32 smb, float (&acc)[2][8][4],
    int fbase, int rg, int ch, int lane, int tid){
  #pragma unroll
  for (int mi=0;mi<2;mi++)
    #pragma unroll
    for (int nt=0;nt<8;nt++)
      #pragma unroll
      for (int j=0;j<4;j++) acc[mi][nt][j]=0.0f;
  const unsigned char* wsrc = g_wp + (size_t)fbase*32768 + (size_t)tid*64;
  const u32 wdst = smb + OFF_W + (u32)tid*64;
  CPA4(wdst, wsrc);
  CP_COMMIT();
  if (KH > 1) CPA4(wdst + 32768, wsrc + 32768);
  CP_COMMIT();
  const int RA0 = rg*32 + (lane&15);
  const u32 xa = (u32)((RA0&7)<<4);
  const u32 aB = smb + OFF_A + (u32)RA0*128;
  const int RB0 = ch*64 + (lane&15);
  const u32 xb = (u32)((RB0&6)<<3);
  const u32 c16 = (u32)((lane>>4)*16);
  int slot = 0, pslot = 2;
  #pragma unroll 1
  for (int u=0; u<KH; u++){
    CP_WAIT1();
    __syncthreads();
    if (u+2 < KH) CPA4(wdst + (u32)pslot*32768, wsrc + (size_t)(u+2)*32768);
    CP_COMMIT();
    const u32 wB = smb + OFF_W + (u32)slot*32768 + (u32)RB0*64;
    const u32 aC = aB + (u32)((u>>1)*16384);
    #pragma unroll
    for (int step=0; step<2; step++){
      const u32 cbA = (u32)(((u&1)*2 + step)*32) + c16;
      const u32 cbB = (u32)(step*32) + c16;
      u32 AH[2][4], AL[2][4];
      #pragma unroll
      for (int mi=0;mi<2;mi++){
        u32 ad = aC + (u32)(mi*2048) + (cbA ^ xa);
        LDSM4(AH[mi], ad);
        LDSM4(AL[mi], ad + 65536);
      }
      // B double buffer: Bbuf[x][0..3]=BH, [4..7]=BL
      u32 B0[8], B1[8];
      {
        u32 bd = wB + (cbB ^ xb);
        LDSM4(&B0[0], bd);
        LDSM4(&B0[4], bd + 16384);
      }
      #pragma unroll
      for (int g=0; g<4; g++){
        u32* Bc = (g & 1) ? B1 : B0;
        u32* Bn = (g & 1) ? B0 : B1;
        u32 bdn = wB + (u32)((g+1)*1024) + (cbB ^ xb);
        // term 0: Ah*Bh across 4 independent acc tiles
        #pragma unroll
        for (int mi=0;mi<2;mi++)
          #pragma unroll
          for (int j=0;j<2;j++)
            MMA(acc[mi][g*2+j], AH[mi], Bc[j], Bc[j+2]);
        if (g < 3) LDSM4(&Bn[0], bdn);           // prefetch next BH
        // term 1: Al*Bh
        #pragma unroll
        for (int mi=0;mi<2;mi++)
          #pragma unroll
          for (int j=0;j<2;j++)
            MMA(acc[mi][g*2+j], AL[mi], Bc[j], Bc[j+2]);
        if (g < 3) LDSM4(&Bn[4], bdn + 16384);   // prefetch next BL
        // term 2: Ah*Bl
        #pragma unroll
        for (int mi=0;mi<2;mi++)
          #pragma unroll
          for (int j=0;j<2;j++)
            MMA(acc[mi][g*2+j], AH[mi], Bc[j+4], Bc[j+6]);
      }
    }
    slot  = (slot==2)  ? 0 : slot+1;
    pslot = (pslot==2) ? 0 : pslot+1;
  }
}

// ghost batch norm (biases cancel; dropped upstream); CA/CB indexed by n'.
__device__ __forceinline__ void epi_gbn(char* smem, float (&acc)[2][8][4],
    const float* __restrict__ gw, const float* __restrict__ gb,
    int rg, int ch, int lane){
  __syncthreads();
  float* PS=(float*)(smem+OFF_PS);
  float* PQ=(float*)(smem+OFF_PQ);
  #pragma unroll
  for (int nt=0;nt<8;nt++){
    float s0=0,s1=0,q0=0,q1=0;
    #pragma unroll
    for (int mi=0;mi<2;mi++){
      s0+=acc[mi][nt][0]+acc[mi][nt][2];
      s1+=acc[mi][nt][1]+acc[mi][nt][3];
      q0+=acc[mi][nt][0]*acc[mi][nt][0]+acc[mi][nt][2]*acc[mi][nt][2];
      q1+=acc[mi][nt][1]*acc[mi][nt][1]+acc[mi][nt][3]*acc[mi][nt][3];
    }
    #pragma unroll
    for (int off=4;off<32;off<<=1){
      s0+=__shfl_xor_sync(~0u,s0,off); s1+=__shfl_xor_sync(~0u,s1,off);
      q0+=__shfl_xor_sync(~0u,q0,off); q1+=__shfl_xor_sync(~0u,q1,off);
    }
    if (lane<4){
      int cc = ch*64 + nt*8 + lane*2;
      PS[rg*256+cc]=s0; PS[rg*256+cc+1]=s1;
      PQ[rg*256+cc]=q0; PQ[rg*256+cc+1]=q1;
    }
  }
  __syncthreads();
  if (threadIdx.x < 256){
    int np=threadIdx.x;
    float sum=PS[np]+PS[256+np]+PS[512+np]+PS[768+np];
    float sq =PQ[np]+PQ[256+np]+PQ[512+np]+PQ[768+np];
    float mean=sum*(1.0f/128.0f);
    float var = sq*(1.0f/128.0f)-mean*mean;
    int q=np>>6, e=np&63;
    int d = (e<32) ? q*32+e : 128+q*32+(e-32);
    float A=rsqrtf(var+EPS_F)*gw[d];
    ((float*)(smem+OFF_CA))[np]=A;
    ((float*)(smem+OFF_CB))[np]=gb[d]-mean*A;
  }
  __syncthreads();
  const float* CA=(const float*)(smem+OFF_CA);
  const float* CB=(const float*)(smem+OFF_CB);
  #pragma unroll
  for (int nt=0;nt<8;nt++){
    int cc=ch*64+nt*8+(lane&3)*2;
    float a0=CA[cc],a1=CA[cc+1],b0=CB[cc],b1=CB[cc+1];
    #pragma unroll
    for (int mi=0;mi<2;mi++){
      acc[mi][nt][0]=acc[mi][nt][0]*a0+b0;
      acc[mi][nt][1]=acc[mi][nt][1]*a1+b1;
      acc[mi][nt][2]=acc[mi][nt][2]*a0+b0;
      acc[mi][nt][3]=acc[mi][nt][3]*a1+b1;
    }
  }
}

// GLU (register-local u,g pairs) + optional residual + tiles / final output
__device__ __forceinline__ void tail_store(char* smem, float (&acc)[2][8][4],
    int rg, int ch, int lane, size_t rowbase, float* out, int mode){
  #pragma unroll
  for (int nt=0; nt<4; nt++){
    int d = ch*32 + nt*8 + (lane&3)*2;   // h col (0..127)
    int ck = d>>6, cb = (d&63)*2;
    #pragma unroll
    for (int s=0;s<4;s++){
      int mi=s>>1, jh=s&1;
      int r = rg*32 + mi*16 + jh*8 + (lane>>2);
      float U0=acc[mi][nt][jh*2], U1=acc[mi][nt][jh*2+1];
      float G0=acc[mi][nt+4][jh*2], G1=acc[mi][nt+4][jh*2+1];
      float h0 = U0*sigf(G0), h1 = U1*sigf(G1);
      u32 off = (u32)(ck*16384 + r*128 + (cb ^ ((r&7)<<4)));
      u32* tH = (u32*)(smem + OFF_A + off);
      u32* tL = (u32*)(smem + OFF_ALO + off);
      if (mode){
        u32 hp=*tH, lp=*tL;
        h0 = S05C*((bflo(hp)+bflo(lp)) + h0);
        h1 = S05C*((bfhi(hp)+bfhi(lp)) + h1);
      }
      if (mode==2){
        if (d < 64)
          *(float2*)(out + (rowbase+r)*64 + d) = make_float2(h0,h1);
        else
          *(float2*)(out + (size_t)N_TOT*64 + (rowbase+r)*64 + (d-64)) =
              make_float2(fmaxf(h0,0.0f), fmaxf(h1,0.0f));
      } else {
        u32 hp,lp; split2(h0,h1,hp,lp);
        *tH=hp; *tL=lp;
      }
    }
  }
}

__global__ void __launch_bounds__(512,1)
tabnet_mma(const float* __restrict__ x, const float* __restrict__ a,
           const float* __restrict__ prior,
           const float* __restrict__ gwa, const float* __restrict__ gba,
           const float* __restrict__ gw1, const float* __restrict__ gb1,
           const float* __restrict__ gw2, const float* __restrict__ gb2,
           const float* __restrict__ gw3, const float* __restrict__ gb3,
           const float* __restrict__ gw4, const float* __restrict__ gb4,
           float* __restrict__ out){
  extern __shared__ char smem[];
  const int tid=threadIdx.x, warp=tid>>5, lane=tid&31;
  const int rg=warp&3, ch=warp>>2;
  const u32 smb=smem_u32(smem);
  const size_t rowbase=(size_t)blockIdx.x*VBS;

  // stage `a` (128x64) -> A chunk 0 (hi) / +65536 (lo)
  for (int idx=tid; idx<128*32; idx+=512){
    int r=idx>>5, p=idx&31;
    float2 v=*(const float2*)(a+(rowbase+r)*64+p*2);
    u32 hp,lp; split2(v.x,v.y,hp,lp);
    u32 off=(u32)(r*128 + ((p*4) ^ ((r&7)<<4)));
    *(u32*)(smem+OFF_A+off)=hp;
    *(u32*)(smem+OFF_ALO+off)=lp;
  }
  __syncthreads();

  float acc[2][8][4];
  // ---- attention GEMM (K=64) + GBN ----
  run_gemm<2>(smb,acc,0,rg,ch,lane,tid);
  epi_gbn(smem,acc,gwa,gba,rg,ch,lane);

  // z = gbn*prior ; per-row sum/max/min for closed-form sparsemax
  const float* priorB = prior + rowbase*256;
  float rs[4]={0,0,0,0};
  float rmx[4]={-3.4e38f,-3.4e38f,-3.4e38f,-3.4e38f};
  float rmn[4]={3.4e38f,3.4e38f,3.4e38f,3.4e38f};
  #pragma unroll
  for (int nt=0;nt<8;nt++){
    int e = nt*8 + (lane&3)*2;
    int d = (e<32) ? ch*32+e : 128+ch*32+(e-32);
    #pragma unroll
    for (int s=0;s<4;s++){
      int mi=s>>1, jh=s&1;
      int r = rg*32 + mi*16 + jh*8 + (lane>>2);
      float2 pv=*(const float2*)(priorB+r*256+d);
      float* A0=&acc[mi][nt][jh*2];
      A0[0]*=pv.x; A0[1]*=pv.y;
      rs[s]+=A0[0]+A0[1];
      rmx[s]=fmaxf(rmx[s],fmaxf(A0[0],A0[1]));
      rmn[s]=fminf(rmn[s],fminf(A0[0],A0[1]));
    }
  }
  #pragma unroll
  for (int off=1;off<4;off<<=1){
    #pragma unroll
    for (int s=0;s<4;s++){
      rs[s]+=__shfl_xor_sync(~0u,rs[s],off);
      rmx[s]=fmaxf(rmx[s],__shfl_xor_sync(~0u,rmx[s],off));
      rmn[s]=fminf(rmn[s],__shfl_xor_sync(~0u,rmn[s],off));
    }
  }
  float* REX=(float*)(smem+OFF_REX);
  float* TAU=(float*)(smem+OFF_TAU);
  if ((lane&3)==0){
    #pragma unroll
    for (int s=0;s<4;s++){
      int mi=s>>1, jh=s&1;
      int r = rg*32 + mi*16 + jh*8 + (lane>>2);
      REX[ch*384+r]=rs[s]; REX[ch*384+128+r]=rmx[s]; REX[ch*384+256+r]=rmn[s];
    }
  }
  __syncthreads();
  if (tid<128){
    float S=REX[tid]+REX[384+tid]+REX[768+tid]+REX[1152+tid];
    float MX=fmaxf(fmaxf(REX[128+tid],REX[512+tid]),
                   fmaxf(REX[896+tid],REX[1280+tid]));
    float MN=fminf(fminf(REX[256+tid],REX[640+tid]),
                   fminf(REX[1024+tid],REX[1408+tid]));
    // kz = 255 iff 1 + 255*max - sum > 0 (condition monotone in rank)
    TAU[tid]=(1.0f+255.0f*MX-S>0.0f) ? (S+1.0f)*(1.0f/255.0f) : (MN+1.0f)/0.0f;
  }
  __syncthreads();

  // m, new_prior ; X1 = x*m -> A chunks 0..3
  {
    const float* xB = x + rowbase*256;
    float* outM = out + (size_t)N_TOT*384 + rowbase*256;
    float* outP = out + (size_t)N_TOT*128 + rowbase*256;
    #pragma unroll
    for (int nt=0;nt<8;nt++){
      int e = nt*8 + (lane&3)*2;
      int d = (e<32) ? ch*32+e : 128+ch*32+(e-32);
      int ck = d>>6, cb = (d&63)*2;
      #pragma unroll
      for (int s=0;s<4;s++){
        int mi=s>>1, jh=s&1;
        int r = rg*32 + mi*16 + jh*8 + (lane>>2);
        float tau=TAU[r];
        float* A0=&acc[mi][nt][jh*2];
        float m0=fmaxf(A0[0]-tau,0.0f), m1=fmaxf(A0[1]-tau,0.0f);
        *(float2*)(outM+r*256+d)=make_float2(m0,m1);
        float2 pv=*(const float2*)(priorB+r*256+d);
        *(float2*)(outP+r*256+d)=make_float2(pv.x*(GAMMA_F-m0),pv.y*(GAMMA_F-m1));
        float2 xv=*(const float2*)(xB+r*256+d);
        u32 hp,lp; split2(xv.x*m0,xv.y*m1,hp,lp);
        u32 off=(u32)(ck*16384 + r*128 + (cb ^ ((r&7)<<4)));
        *(u32*)(smem+OFF_A+off)=hp;
        *(u32*)(smem+OFF_ALO+off)=lp;
      }
    }
  }

  // ---- s1 GEMM (K=256) + GBN + GLU -> h tiles (chunks 0,1) ----
  run_gemm<8>(smb,acc,2,rg,ch,lane,tid);
  epi_gbn(smem,acc,gw1,gb1,rg,ch,lane);
  tail_store(smem,acc,rg,ch,lane,rowbase,out,0);

  // ---- three residual GLU layers (K=128) ----
  run_gemm<4>(smb,acc,10,rg,ch,lane,tid);
  epi_gbn(smem,acc,gw2,gb2,rg,ch,lane);
  tail_store(smem,acc,rg,ch,lane,rowbase,out,1);

  run_gemm<4>(smb,acc,14,rg,ch,lane,tid);
  epi_gbn(smem,acc,gw3,gb3,rg,ch,lane);
  tail_store(smem,acc,rg,ch,lane,rowbase,out,1);

  run_gemm<4>(smb,acc,18,rg,ch,lane,tid);
  epi_gbn(smem,acc,gw4,gb4,rg,ch,lane);
  tail_store(smem,acc,rg,ch,lane,rowbase,out,2);
}

extern "C" void kernel_launch(void* const* d_in, const int* in_sizes, int n_in,
                              void* d_out, int out_size){
  (void)in_sizes; (void)n_in; (void)out_size;
  const float* x     = (const float*)d_in[0];
  const float* a     = (const float*)d_in[1];
  const float* prior = (const float*)d_in[2];
  const float* w_att = (const float*)d_in[3];
  const float* gwa   = (const float*)d_in[5];
  const float* gba   = (const float*)d_in[6];
  const float* w_s1  = (const float*)d_in[7];
  const float* gw1   = (const float*)d_in[9];
  const float* gb1   = (const float*)d_in[10];
  const float* w_s2  = (const float*)d_in[11];
  const float* gw2   = (const float*)d_in[13];
  const float* gb2   = (const float*)d_in[14];
  const float* w_d1  = (const float*)d_in[15];
  const float* gw3   = (const float*)d_in[17];
  const float* gb3   = (const float*)d_in[18];
  const float* w_d2  = (const float*)d_in[19];
  const float* gw4   = (const float*)d_in[21];
  const float* gb4   = (const float*)d_in[22];

  prep_weights<<<11, 256>>>(w_att, w_s1, w_s2, w_d1, w_d2);
  cudaFuncSetAttribute(tabnet_mma,
      cudaFuncAttributeMaxDynamicSharedMemorySize, SMEM_TOTAL);
  tabnet_mma<<<NCHUNK, 512, SMEM_TOTAL>>>(
      x, a, prior, gwa, gba, gw1, gb1, gw2, gb2, gw3, gb3, gw4, gb4,
      (float*)d_out);
}

// round 17
// speedup vs baseline: 1.1612x; 1.1612x over previous
#include <cuda_runtime.h>
#include <cuda_bf16.h>

#define N_TOT 65536
#define EPS_F 1e-5f
#define GAMMA_F 1.5f
#define S05C 0.70710678118654752440f

typedef unsigned int u32;

// per-CTA smem (bytes); CTA owns 64 rows of a 128-row ghost batch.
// NOTHING aliases: A | W ring-2 | dedicated stats+inbox.
#define OFF_A    0        // A hi: 4 chunks x 8KB (64 rows x 64 k, 128B swizzled rows)
#define OFF_ALO  32768    // A lo
#define OFF_W    65536    // W ring: 2 x 16KB k16 slices (8KB hi + 8KB lo)
#define ST_PS    98304    // 2 x 256 f32
#define ST_PQ    100352
#define ST_PUB   102400   // 2 parity x (256 sum + 256 sq) cluster inbox (dedicated!)
#define ST_CA    106496
#define ST_CB    107520
#define ST_REX   108544   // 4 quarters x 3 x 64
#define ST_TAU   111616
#define SMEM_TOTAL 114688

// weights: 44 k16 slices x 16KB (8KB hi + 8KB lo), permuted cols, lane-swizzled
__device__ __align__(16) unsigned char g_wp[44*16384];

__device__ __forceinline__ u32 smem_u32(const void* p){
  u32 a; asm("{ .reg .u64 t; cvta.to.shared.u64 t, %1; cvt.u32.u64 %0, t; }"
             : "=r"(a) : "l"(p)); return a;
}
__device__ __forceinline__ u32 ctarank(){
  u32 r; asm("mov.u32 %0, %%cluster_ctarank;" : "=r"(r)); return r;
}
__device__ __forceinline__ u32 mapa_sh(u32 addr, u32 rank){
  u32 r; asm("mapa.shared::cluster.u32 %0, %1, %2;" : "=r"(r) : "r"(addr), "r"(rank));
  return r;
}
__device__ __forceinline__ void st_cluster(u32 addr, float v){
  asm volatile("st.shared::cluster.f32 [%0], %1;" :: "r"(addr), "f"(v) : "memory");
}
#define CLUSTER_SYNC() do{ \
  asm volatile("barrier.cluster.arrive.aligned;" ::: "memory"); \
  asm volatile("barrier.cluster.wait.aligned;" ::: "memory"); }while(0)

__device__ __forceinline__ float sigf(float x){
  return __fdividef(1.0f, 1.0f + __expf(-x));
}
__device__ __forceinline__ void split2(float a, float b, u32& hp, u32& lp){
  __nv_bfloat16 ha=__float2bfloat16(a), hb=__float2bfloat16(b);
  __nv_bfloat16 la=__float2bfloat16(a-__bfloat162float(ha));
  __nv_bfloat16 lb=__float2bfloat16(b-__bfloat162float(hb));
  hp = ((u32)__bfloat16_as_ushort(hb)<<16) | __bfloat16_as_ushort(ha);
  lp = ((u32)__bfloat16_as_ushort(lb)<<16) | __bfloat16_as_ushort(la);
}
__device__ __forceinline__ float bflo(u32 v){
  return __bfloat162float(__ushort_as_bfloat16((unsigned short)(v&0xffffu)));
}
__device__ __forceinline__ float bfhi(u32 v){
  return __bfloat162float(__ushort_as_bfloat16((unsigned short)(v>>16)));
}

#define LDSM4(r, a) \
  asm volatile("ldmatrix.sync.aligned.m8n8.x4.shared.b16 {%0,%1,%2,%3}, [%4];" \
    : "=r"((r)[0]),"=r"((r)[1]),"=r"((r)[2]),"=r"((r)[3]) : "r"(a))
#define MMA(d, a, b0, b1) \
  asm volatile("mma.sync.aligned.m16n8k16.row.col.f32.bf16.bf16.f32 " \
    "{%0,%1,%2,%3},{%4,%5,%6,%7},{%8,%9},{%0,%1,%2,%3};" \
    : "+f"((d)[0]),"+f"((d)[1]),"+f"((d)[2]),"+f"((d)[3]) \
    : "r"((a)[0]),"r"((a)[1]),"r"((a)[2]),"r"((a)[3]),"r"(b0),"r"(b1))
#define CPA(dst, src) \
  asm volatile("cp.async.cg.shared.global [%0], [%1], 16;" :: "r"(dst), "l"(src))
#define CPA4(dst, src) do{ CPA((dst),(src)); CPA((dst)+16,(src)+16); \
  CPA((dst)+32,(src)+32); CPA((dst)+48,(src)+48);}while(0)
#define CP_COMMIT() asm volatile("cp.async.commit_group;" ::: "memory")
#define CP_WAIT1()  asm volatile("cp.async.wait_group 1;" ::: "memory")

// column permutation: quarter q owns u-cols d=q*32..+31 (n'=q*64+pos) and
// g-cols d=128+q*32..+31 (n'=q*64+32+pos)
__device__ __forceinline__ int permn(int n){
  return (n < 128) ? ((n>>5)*64 + (n&31))
                   : (((n-128)>>5)*64 + 32 + ((n-128)&31));
}

// prep: fp32 W -> bf16 hi/lo, permuted cols, 16KB k16 slices.
// element (n', kk in 0..15) of slice fs at byte:
//   n'*32 + ((kk>>3)*16 ^ ((n'&4)<<2)) + (kk&7)*2   (hi; lo at +8192)
__global__ void prep_weights(const float* __restrict__ w_att,
                             const float* __restrict__ w_s1,
                             const float* __restrict__ w_s2,
                             const float* __restrict__ w_d1,
                             const float* __restrict__ w_d2){
  int t = blockIdx.x; const float* W; int K, kc;
  if (t == 0)     { W = w_att; K = 64;  kc = 0;   }
  else if (t < 5) { W = w_s1;  K = 256; kc = t-1; }
  else if (t < 7) { W = w_s2;  K = 128; kc = t-5; }
  else if (t < 9) { W = w_d1;  K = 128; kc = t-7; }
  else            { W = w_d2;  K = 128; kc = t-9; }
  for (int idx = threadIdx.x; idx < 16384; idx += 256){
    int n = idx >> 6, k = idx & 63;
    float w = W[n*K + kc*64 + k];
    __nv_bfloat16 hi = __float2bfloat16(w);
    __nv_bfloat16 lo = __float2bfloat16(w - __bfloat162float(hi));
    int np = permn(n);
    int fs = t*4 + (k>>4);
    int kk = k & 15;
    int inner = np*32 + (((kk>>3)*16) ^ ((np&4)<<2)) + (kk&7)*2;
    *(__nv_bfloat16*)(g_wp + (size_t)fs*16384 + inner)        = hi;
    *(__nv_bfloat16*)(g_wp + (size_t)fs*16384 + 8192 + inner) = lo;
  }
}

// C[64 x 256(n')] = A[64 x KH*16] * W^T, 3-term bf16 split, ring-2 cp.async.
template<int KH>
__device__ __forceinline__ void run_gemm(u32 smb, float (&acc)[2][8][4],
    int fbase, int rg, int ch, int lane, int tid){
  #pragma unroll
  for (int mi=0;mi<2;mi++)
    #pragma unroll
    for (int nt=0;nt<8;nt++)
      #pragma unroll
      for (int j=0;j<4;j++) acc[mi][nt][j]=0.0f;
  const unsigned char* wsrc = g_wp + (size_t)fbase*16384 + (size_t)tid*64;
  const u32 wdst = smb + OFF_W + (u32)tid*64;
  CPA4(wdst, wsrc);
  CP_COMMIT();
  if (KH > 1) CPA4(wdst + 16384, wsrc + 16384);
  CP_COMMIT();
  const int RA0 = rg*32 + (lane&15);
  const u32 xa = (u32)((RA0&7)<<4);
  const u32 aB = smb + OFF_A + (u32)RA0*128;
  const u32 c16 = (u32)((lane>>4)*16);
  const int brow16 = (((lane>>3)&1)<<3) + (lane&7);
  const u32 bswz = c16 ^ (u32)((brow16&4)<<2);
  const u32 bA = (u32)((ch*64 + brow16)*32) + bswz;
  #pragma unroll 1
  for (int u=0; u<KH; u++){
    // groups complete in commit order: <=1 pending => slice u resident.
    CP_WAIT1();
    __syncthreads();
    const u32 wB = smb + OFF_W + (u32)((u&1)*16384) + bA;
    const u32 ad0 = aB + (u32)((u>>2)*8192) + ((((u32)(u&3)*32) + c16) ^ xa);
    u32 AH[2][4], AL[2][4];
    #pragma unroll
    for (int mi=0;mi<2;mi++){
      LDSM4(AH[mi], ad0 + (u32)(mi*2048));
      LDSM4(AL[mi], ad0 + (u32)(mi*2048) + 32768);
    }
    #pragma unroll
    for (int g=0; g<4; g++){
      u32 BH[4], BL[4];
      LDSM4(BH, wB + (u32)(g*512));
      LDSM4(BL, wB + (u32)(g*512) + 8192);
      #pragma unroll
      for (int mi=0;mi<2;mi++)
        #pragma unroll
        for (int j=0;j<2;j++)
          MMA(acc[mi][g*2+j], AH[mi], BH[j], BH[j+2]);
      #pragma unroll
      for (int mi=0;mi<2;mi++)
        #pragma unroll
        for (int j=0;j<2;j++)
          MMA(acc[mi][g*2+j], AL[mi], BH[j], BH[j+2]);
      #pragma unroll
      for (int mi=0;mi<2;mi++)
        #pragma unroll
        for (int j=0;j<2;j++)
          MMA(acc[mi][g*2+j], AH[mi], BL[j], BL[j+2]);
    }
    __syncthreads();   // all reads of slot u&1 done before refill below
    if (u+2 < KH) CPA4(wdst + (u32)((u&1)*16384), wsrc + (size_t)(u+2)*16384);
    CP_COMMIT();
  }
}

// ghost batch norm over 128 rows = own 64 + peer 64. Column partials exchanged
// through the DEDICATED peer inbox (never aliased). Parity double-buffers the
// inbox; the cluster-barrier chain forbids same-parity overwrite before read.
__device__ __forceinline__ void epi_gbn(char* smem, u32 smb, float (&acc)[2][8][4],
    const float* __restrict__ gw, const float* __restrict__ gb,
    int rg, int ch, int lane, int par, u32 prank){
  __syncthreads();
  float* PS=(float*)(smem+ST_PS);
  float* PQ=(float*)(smem+ST_PQ);
  #pragma unroll
  for (int nt=0;nt<8;nt++){
    float s0=0,s1=0,q0=0,q1=0;
    #pragma unroll
    for (int mi=0;mi<2;mi++){
      s0+=acc[mi][nt][0]+acc[mi][nt][2];
      s1+=acc[mi][nt][1]+acc[mi][nt][3];
      q0+=acc[mi][nt][0]*acc[mi][nt][0]+acc[mi][nt][2]*acc[mi][nt][2];
      q1+=acc[mi][nt][1]*acc[mi][nt][1]+acc[mi][nt][3]*acc[mi][nt][3];
    }
    #pragma unroll
    for (int off=4;off<32;off<<=1){
      s0+=__shfl_xor_sync(~0u,s0,off); s1+=__shfl_xor_sync(~0u,s1,off);
      q0+=__shfl_xor_sync(~0u,q0,off); q1+=__shfl_xor_sync(~0u,q1,off);
    }
    if (lane<4){
      int cc = ch*64 + nt*8 + lane*2;
      PS[rg*256+cc]=s0; PS[rg*256+cc+1]=s1;
      PQ[rg*256+cc]=q0; PQ[rg*256+cc+1]=q1;
    }
  }
  __syncthreads();
  {
    int c = threadIdx.x;           // 256 threads <-> 256 n' columns
    float ls = PS[c]+PS[256+c];
    float lq = PQ[c]+PQ[256+c];
    u32 inbox = smb + ST_PUB + (u32)par*2048 + (u32)c*4;
    u32 pb = mapa_sh(inbox, prank);
    st_cluster(pb, ls);
    st_cluster(pb + 1024, lq);
    CLUSTER_SYNC();
    const float* INB = (const float*)(smem + ST_PUB + par*2048);
    float sum = ls + INB[c];
    float sq  = lq + INB[256+c];
    float mean = sum*(1.0f/128.0f);
    float var  = sq*(1.0f/128.0f) - mean*mean;
    int q=c>>6, e=c&63;
    int d = (e<32) ? q*32+e : 128+q*32+(e-32);
    float A = rsqrtf(var+EPS_F)*gw[d];
    ((float*)(smem+ST_CA))[c] = A;
    ((float*)(smem+ST_CB))[c] = gb[d] - mean*A;
  }
  __syncthreads();
  const float* CA=(const float*)(smem+ST_CA);
  const float* CB=(const float*)(smem+ST_CB);
  #pragma unroll
  for (int nt=0;nt<8;nt++){
    int cc=ch*64+nt*8+(lane&3)*2;
    float a0=CA[cc],a1=CA[cc+1],b0=CB[cc],b1=CB[cc+1];
    #pragma unroll
    for (int mi=0;mi<2;mi++){
      acc[mi][nt][0]=acc[mi][nt][0]*a0+b0;
      acc[mi][nt][1]=acc[mi][nt][1]*a1+b1;
      acc[mi][nt][2]=acc[mi][nt][2]*a0+b0;
      acc[mi][nt][3]=acc[mi][nt][3]*a1+b1;
    }
  }
}

// GLU (register-local u,g pairs) + optional residual + tiles / final output
__device__ __forceinline__ void tail_store(char* smem, float (&acc)[2][8][4],
    int rg, int ch, int lane, size_t growbase, float* out, int mode){
  #pragma unroll
  for (int nt=0; nt<4; nt++){
    int d = ch*32 + nt*8 + (lane&3)*2;   // h col (0..127)
    int ck = d>>6, cb = (d&63)*2;
    #pragma unroll
    for (int s=0;s<4;s++){
      int mi=s>>1, jh=s&1;
      int r = rg*32 + mi*16 + jh*8 + (lane>>2);   // local row 0..63
      float U0=acc[mi][nt][jh*2], U1=acc[mi][nt][jh*2+1];
      float G0=acc[mi][nt+4][jh*2], G1=acc[mi][nt+4][jh*2+1];
      float h0 = U0*sigf(G0), h1 = U1*sigf(G1);
      u32 off = (u32)(ck*8192 + r*128 + (cb ^ ((r&7)<<4)));
      u32* tH = (u32*)(smem + OFF_A + off);
      u32* tL = (u32*)(smem + OFF_ALO + off);
      if (mode){
        u32 hp=*tH, lp=*tL;
        h0 = S05C*((bflo(hp)+bflo(lp)) + h0);
        h1 = S05C*((bfhi(hp)+bfhi(lp)) + h1);
      }
      if (mode==2){
        if (d < 64)
          *(float2*)(out + (growbase+r)*64 + d) = make_float2(h0,h1);
        else
          *(float2*)(out + (size_t)N_TOT*64 + (growbase+r)*64 + (d-64)) =
              make_float2(fmaxf(h0,0.0f), fmaxf(h1,0.0f));
      } else {
        u32 hp,lp; split2(h0,h1,hp,lp);
        *tH=hp; *tL=lp;
      }
    }
  }
}

__global__ void __launch_bounds__(256,2) __cluster_dims__(2,1,1)
tabnet_mma(const float* __restrict__ x, const float* __restrict__ a,
           const float* __restrict__ prior,
           const float* __restrict__ gwa, const float* __restrict__ gba,
           const float* __restrict__ gw1, const float* __restrict__ gb1,
           const float* __restrict__ gw2, const float* __restrict__ gb2,
           const float* __restrict__ gw3, const float* __restrict__ gb3,
           const float* __restrict__ gw4, const float* __restrict__ gb4,
           float* __restrict__ out){
  extern __shared__ char smem[];
  const int tid=threadIdx.x, warp=tid>>5, lane=tid&31;
  const int rg=warp&1, ch=warp>>1;
  const u32 smb=smem_u32(smem);
  const u32 prank = ctarank() ^ 1u;
  const size_t growbase = (size_t)blockIdx.x * 64;   // 64 global rows per CTA

  // stage `a` (own 64 rows x 64 cols) -> A chunk 0 (hi) / lo
  for (int idx=tid; idx<64*32; idx+=256){
    int r=idx>>5, p=idx&31;
    float2 v=*(const float2*)(a+(growbase+r)*64+p*2);
    u32 hp,lp; split2(v.x,v.y,hp,lp);
    u32 off=(u32)(r*128 + ((p*4) ^ ((r&7)<<4)));
    *(u32*)(smem+OFF_A+off)=hp;
    *(u32*)(smem+OFF_ALO+off)=lp;
  }
  __syncthreads();

  float acc[2][8][4];
  // ---- attention GEMM (K=64, slices 0..3) + GBN ----
  run_gemm<4>(smb,acc,0,rg,ch,lane,tid);
  epi_gbn(smem,smb,acc,gwa,gba,rg,ch,lane,0,prank);

  // z = gbn*prior ; per-row sum/max/min for closed-form sparsemax (rows local)
  const float* priorB = prior + growbase*256;
  float rs[4]={0,0,0,0};
  float rmx[4]={-3.4e38f,-3.4e38f,-3.4e38f,-3.4e38f};
  float rmn[4]={3.4e38f,3.4e38f,3.4e38f,3.4e38f};
  #pragma unroll
  for (int nt=0;nt<8;nt++){
    int e = nt*8 + (lane&3)*2;
    int d = (e<32) ? ch*32+e : 128+ch*32+(e-32);
    #pragma unroll
    for (int s=0;s<4;s++){
      int mi=s>>1, jh=s&1;
      int r = rg*32 + mi*16 + jh*8 + (lane>>2);
      float2 pv=*(const float2*)(priorB+r*256+d);
      float* A0=&acc[mi][nt][jh*2];
      A0[0]*=pv.x; A0[1]*=pv.y;
      rs[s]+=A0[0]+A0[1];
      rmx[s]=fmaxf(rmx[s],fmaxf(A0[0],A0[1]));
      rmn[s]=fminf(rmn[s],fminf(A0[0],A0[1]));
    }
  }
  #pragma unroll
  for (int off=1;off<4;off<<=1){
    #pragma unroll
    for (int s=0;s<4;s++){
      rs[s]+=__shfl_xor_sync(~0u,rs[s],off);
      rmx[s]=fmaxf(rmx[s],__shfl_xor_sync(~0u,rmx[s],off));
      rmn[s]=fminf(rmn[s],__shfl_xor_sync(~0u,rmn[s],off));
    }
  }
  float* REX=(float*)(smem+ST_REX);
  float* TAU=(float*)(smem+ST_TAU);
  if ((lane&3)==0){
    #pragma unroll
    for (int s=0;s<4;s++){
      int mi=s>>1, jh=s&1;
      int r = rg*32 + mi*16 + jh*8 + (lane>>2);
      REX[ch*192+r]=rs[s]; REX[ch*192+64+r]=rmx[s]; REX[ch*192+128+r]=rmn[s];
    }
  }
  __syncthreads();
  if (tid<64){
    float S=REX[tid]+REX[192+tid]+REX[384+tid]+REX[576+tid];
    float MX=fmaxf(fmaxf(REX[64+tid],REX[256+tid]),
                   fmaxf(REX[448+tid],REX[640+tid]));
    float MN=fminf(fminf(REX[128+tid],REX[320+tid]),
                   fminf(REX[512+tid],REX[704+tid]));
    // kz = 255 iff 1 + 255*max - sum > 0 (condition monotone in rank)
    TAU[tid]=(1.0f+255.0f*MX-S>0.0f) ? (S+1.0f)*(1.0f/255.0f) : (MN+1.0f)/0.0f;
  }
  __syncthreads();

  // m, new_prior ; X1 = x*m -> A chunks 0..3
  {
    const float* xB = x + growbase*256;
    float* outM = out + (size_t)N_TOT*384 + growbase*256;
    float* outP = out + (size_t)N_TOT*128 + growbase*256;
    #pragma unroll
    for (int nt=0;nt<8;nt++){
      int e = nt*8 + (lane&3)*2;
      int d = (e<32) ? ch*32+e : 128+ch*32+(e-32);
      int ck = d>>6, cb = (d&63)*2;
      #pragma unroll
      for (int s=0;s<4;s++){
        int mi=s>>1, jh=s&1;
        int r = rg*32 + mi*16 + jh*8 + (lane>>2);
        float tau=TAU[r];
        float* A0=&acc[mi][nt][jh*2];
        float m0=fmaxf(A0[0]-tau,0.0f), m1=fmaxf(A0[1]-tau,0.0f);
        *(float2*)(outM+r*256+d)=make_float2(m0,m1);
        float2 pv=*(const float2*)(priorB+r*256+d);
        *(float2*)(outP+r*256+d)=make_float2(pv.x*(GAMMA_F-m0),pv.y*(GAMMA_F-m1));
        float2 xv=*(const float2*)(xB+r*256+d);
        u32 hp,lp; split2(xv.x*m0,xv.y*m1,hp,lp);
        u32 off=(u32)(ck*8192 + r*128 + (cb ^ ((r&7)<<4)));
        *(u32*)(smem+OFF_A+off)=hp;
        *(u32*)(smem+OFF_ALO+off)=lp;
      }
    }
  }

  // ---- s1 GEMM (K=256, slices 4..19) + GBN + GLU -> h tiles (chunks 0,1) ----
  run_gemm<16>(smb,acc,4,rg,ch,lane,tid);
  epi_gbn(smem,smb,acc,gw1,gb1,rg,ch,lane,1,prank);
  tail_store(smem,acc,rg,ch,lane,growbase,out,0);

  // ---- three residual GLU layers (K=128, 8 slices each) ----
  run_gemm<8>(smb,acc,20,rg,ch,lane,tid);
  epi_gbn(smem,smb,acc,gw2,gb2,rg,ch,lane,0,prank);
  tail_store(smem,acc,rg,ch,lane,growbase,out,1);

  run_gemm<8>(smb,acc,28,rg,ch,lane,tid);
  epi_gbn(smem,smb,acc,gw3,gb3,rg,ch,lane,1,prank);
  tail_store(smem,acc,rg,ch,lane,growbase,out,1);

  run_gemm<8>(smb,acc,36,rg,ch,lane,tid);
  epi_gbn(smem,smb,acc,gw4,gb4,rg,ch,lane,0,prank);
  tail_store(smem,acc,rg,ch,lane,growbase,out,2);

  CLUSTER_SYNC();   // keep smem alive until peer's last exchange completes
}

extern "C" void kernel_launch(void* const* d_in, const int* in_sizes, int n_in,
                              void* d_out, int out_size){
  (void)in_sizes; (void)n_in; (void)out_size;
  const float* x     = (const float*)d_in[0];
  const float* a     = (const float*)d_in[1];
  const float* prior = (const float*)d_in[2];
  const float* w_att = (const float*)d_in[3];
  const float* gwa   = (const float*)d_in[5];
  const float* gba   = (const float*)d_in[6];
  const float* w_s1  = (const float*)d_in[7];
  const float* gw1   = (const float*)d_in[9];
  const float* gb1   = (const float*)d_in[10];
  const float* w_s2  = (const float*)d_in[11];
  const float* gw2   = (const float*)d_in[13];
  const float* gb2   = (const float*)d_in[14];
  const float* w_d1  = (const float*)d_in[15];
  const float* gw3   = (const float*)d_in[17];
  const float* gb3   = (const float*)d_in[18];
  const float* w_d2  = (const float*)d_in[19];
  const float* gw4   = (const float*)d_in[21];
  const float* gb4   = (const float*)d_in[22];

  prep_weights<<<11, 256>>>(w_att, w_s1, w_s2, w_d1, w_d2);
  cudaFuncSetAttribute(tabnet_mma,
      cudaFuncAttributeMaxDynamicSharedMemorySize, SMEM_TOTAL);
  tabnet_mma<<<1024, 256, SMEM_TOTAL>>>(
      x, a, prior, gwa, gba, gw1, gb1, gw2, gb2, gw3, gb3, gw4, gb4,
      (float*)d_out);
}